// round 1
// baseline (speedup 1.0000x reference)
#include <cuda_runtime.h>
#include <cstdint>

// Problem dimensions (fixed by the reference setup_inputs)
#define BATCH 2
#define EMB   1024
#define SEQ   2048
#define NH    16
#define DH    64

// Attention smem tile leading dims
#define LQ 68   // multiple of 4 -> float4-aligned rows, conflict-free row reads
#define LV 65   // odd -> conflict-free column (stride-LV) scalar reads

static const int ATTN_SMEM_BYTES = (3 * 64 * LQ + 64 * LV) * (int)sizeof(float);

// Scratch (allocation-free rule: __device__ globals)
__device__ float g_qp[(size_t)BATCH * EMB * SEQ];
__device__ float g_kp[(size_t)BATCH * EMB * SEQ];
__device__ float g_vp[(size_t)BATCH * EMB * SEQ];
__device__ float g_at[(size_t)BATCH * EMB * SEQ];

// ---------------------------------------------------------------------------
// Projection GEMM:  C[b] = alpha * (W @ X[b] + bias)
// W: [M=1024, K=1024] row-major; X[b]: [K, N=2048]; C[b]: [M, N]
// 128x128 block tile, BK=16, 256 threads, 8x8 per thread.
// ---------------------------------------------------------------------------
__global__ void __launch_bounds__(256) proj_gemm(
    const float* __restrict__ W, const float* __restrict__ X,
    const float* __restrict__ bias, float* __restrict__ C, float alpha)
{
    const int K = EMB, N = SEQ;
    __shared__ float As[16][132];   // transposed A tile, padded
    __shared__ float Bs[16][128];

    const int tid = threadIdx.x;
    const float* Xb = X + (size_t)blockIdx.z * EMB * SEQ;
    float*       Cb = C + (size_t)blockIdx.z * EMB * SEQ;
    const int row0 = blockIdx.y * 128;
    const int col0 = blockIdx.x * 128;

    const int ar = tid >> 2, ac = (tid & 3) * 4;   // A loads: rows ar, ar+64
    const int br = tid >> 5, bc = (tid & 31) * 4;  // B loads: rows br, br+8
    const int ty = tid >> 4, tx = tid & 15;        // compute sub-tile

    float acc[8][8];
#pragma unroll
    for (int i = 0; i < 8; i++)
#pragma unroll
        for (int j = 0; j < 8; j++) acc[i][j] = 0.f;

    for (int kt = 0; kt < K; kt += 16) {
        float4 a0 = *(const float4*)&W[(size_t)(row0 + ar) * K + kt + ac];
        float4 a1 = *(const float4*)&W[(size_t)(row0 + ar + 64) * K + kt + ac];
        float4 b0 = *(const float4*)&Xb[(size_t)(kt + br) * N + col0 + bc];
        float4 b1 = *(const float4*)&Xb[(size_t)(kt + br + 8) * N + col0 + bc];

        As[ac + 0][ar] = a0.x; As[ac + 1][ar] = a0.y;
        As[ac + 2][ar] = a0.z; As[ac + 3][ar] = a0.w;
        As[ac + 0][ar + 64] = a1.x; As[ac + 1][ar + 64] = a1.y;
        As[ac + 2][ar + 64] = a1.z; As[ac + 3][ar + 64] = a1.w;
        *(float4*)&Bs[br][bc]     = b0;
        *(float4*)&Bs[br + 8][bc] = b1;
        __syncthreads();

#pragma unroll
        for (int k = 0; k < 16; k++) {
            float a[8], b[8];
            *(float4*)&a[0] = *(const float4*)&As[k][ty * 8];
            *(float4*)&a[4] = *(const float4*)&As[k][ty * 8 + 4];
            *(float4*)&b[0] = *(const float4*)&Bs[k][tx * 8];
            *(float4*)&b[4] = *(const float4*)&Bs[k][tx * 8 + 4];
#pragma unroll
            for (int i = 0; i < 8; i++)
#pragma unroll
                for (int j = 0; j < 8; j++)
                    acc[i][j] += a[i] * b[j];
        }
        __syncthreads();
    }

#pragma unroll
    for (int i = 0; i < 8; i++) {
        const int row = row0 + ty * 8 + i;
        const float bi = bias[row];
        float4 r0, r1;
        r0.x = alpha * (acc[i][0] + bi); r0.y = alpha * (acc[i][1] + bi);
        r0.z = alpha * (acc[i][2] + bi); r0.w = alpha * (acc[i][3] + bi);
        r1.x = alpha * (acc[i][4] + bi); r1.y = alpha * (acc[i][5] + bi);
        r1.z = alpha * (acc[i][6] + bi); r1.w = alpha * (acc[i][7] + bi);
        *(float4*)&Cb[(size_t)row * N + col0 + tx * 8]     = r0;
        *(float4*)&Cb[(size_t)row * N + col0 + tx * 8 + 4] = r1;
    }
}

// ---------------------------------------------------------------------------
// Fused attention for one (b, h, 64-query tile).
// scores[k,q] = sum_c K[c,k]*Q[c,q] + mask[b,k,q]; softmax over k; O = V @ P.
// 256 threads; thread (tk = tid&15, tq = tid>>4):
//   - scores sub-tile: k rows tk*4..+3, q cols tq*4..+3
//   - O sub-tile:      c rows tk+16i,   q cols tq*4..+3
// Each warp owns q columns [8w, 8w+8) exclusively -> softmax state (m, l) is
// warp-replicated registers, no smem, no barriers for softmax.
// ---------------------------------------------------------------------------
__global__ void __launch_bounds__(256) attn_kernel(
    const float* __restrict__ QP, const float* __restrict__ KP,
    const float* __restrict__ VP, const float* __restrict__ MASK,
    float* __restrict__ OUTP)
{
    extern __shared__ float sm[];
    float* Qs = sm;                // [64][LQ]
    float* Ks = Qs + 64 * LQ;      // [64][LQ]
    float* Ps = Ks + 64 * LQ;      // [64][LQ]
    float* Vs = Ps + 64 * LQ;      // [64][LV]

    const int tid = threadIdx.x;
    const int b = blockIdx.z, h = blockIdx.y;
    const int q0 = blockIdx.x * 64;

    const float* Qg = QP + ((size_t)b * EMB + h * DH) * SEQ + q0;
    const float* Kg = KP + ((size_t)b * EMB + h * DH) * SEQ;
    const float* Vg = VP + ((size_t)b * EMB + h * DH) * SEQ;
    const float* Mg = MASK + (size_t)b * SEQ * SEQ + q0;
    float*       Og = OUTP + ((size_t)b * EMB + h * DH) * SEQ + q0;

    const int tk = tid & 15;
    const int tq = tid >> 4;

    // Load Q tile (64 c-rows x 64 q-cols)
#pragma unroll
    for (int it = 0; it < 4; it++) {
        const int e = tid + it * 256;
        const int c = e >> 4, x4 = (e & 15) * 4;
        *(float4*)&Qs[c * LQ + x4] = *(const float4*)&Qg[(size_t)c * SEQ + x4];
    }

    float m_r[4], l_r[4], o_r[4][4];
#pragma unroll
    for (int j = 0; j < 4; j++) { m_r[j] = -1e30f; l_r[j] = 0.f; }
#pragma unroll
    for (int i = 0; i < 4; i++)
#pragma unroll
        for (int j = 0; j < 4; j++) o_r[i][j] = 0.f;

    for (int kt = 0; kt < SEQ / 64; kt++) {
        const int k0 = kt * 64;
        __syncthreads();  // all warps done with previous Ks/Vs
#pragma unroll
        for (int it = 0; it < 4; it++) {
            const int e = tid + it * 256;
            const int c = e >> 4, x4 = (e & 15) * 4;
            *(float4*)&Ks[c * LQ + x4] =
                *(const float4*)&Kg[(size_t)c * SEQ + k0 + x4];
            float4 vv = *(const float4*)&Vg[(size_t)c * SEQ + k0 + x4];
            Vs[c * LV + x4 + 0] = vv.x; Vs[c * LV + x4 + 1] = vv.y;
            Vs[c * LV + x4 + 2] = vv.z; Vs[c * LV + x4 + 3] = vv.w;
        }
        __syncthreads();

        // ---- scores tile: init with mask, accumulate K^T Q over c ----
        float acc[4][4];
#pragma unroll
        for (int i = 0; i < 4; i++) {
            float4 mr = *(const float4*)&Mg[(size_t)(k0 + tk * 4 + i) * SEQ + tq * 4];
            acc[i][0] = mr.x; acc[i][1] = mr.y; acc[i][2] = mr.z; acc[i][3] = mr.w;
        }
#pragma unroll 8
        for (int c = 0; c < 64; c++) {
            float kk[4], qq[4];
            *(float4*)kk = *(const float4*)&Ks[c * LQ + tk * 4];
            *(float4*)qq = *(const float4*)&Qs[c * LQ + tq * 4];
#pragma unroll
            for (int i = 0; i < 4; i++)
#pragma unroll
                for (int j = 0; j < 4; j++)
                    acc[i][j] += kk[i] * qq[j];
        }

        // ---- online softmax (per q column; reduce over tk = low 4 lane bits) ----
        float p[4][4], fs[4];
#pragma unroll
        for (int j = 0; j < 4; j++) {
            float mx = fmaxf(fmaxf(acc[0][j], acc[1][j]), fmaxf(acc[2][j], acc[3][j]));
#pragma unroll
            for (int off = 1; off < 16; off <<= 1)
                mx = fmaxf(mx, __shfl_xor_sync(0xffffffffu, mx, off));
            const float mnew = fmaxf(m_r[j], mx);
            fs[j] = __expf(m_r[j] - mnew);
            float ts = 0.f;
#pragma unroll
            for (int i = 0; i < 4; i++) {
                p[i][j] = __expf(acc[i][j] - mnew);
                ts += p[i][j];
            }
#pragma unroll
            for (int off = 1; off < 16; off <<= 1)
                ts += __shfl_xor_sync(0xffffffffu, ts, off);
            l_r[j] = l_r[j] * fs[j] + ts;
            m_r[j] = mnew;
        }

        // Ps is warp-private in the q direction: no cross-warp barrier needed
#pragma unroll
        for (int i = 0; i < 4; i++)
            *(float4*)&Ps[(tk * 4 + i) * LQ + tq * 4] =
                make_float4(p[i][0], p[i][1], p[i][2], p[i][3]);

#pragma unroll
        for (int i = 0; i < 4; i++)
#pragma unroll
            for (int j = 0; j < 4; j++) o_r[i][j] *= fs[j];
        __syncwarp();

        // ---- O += V @ P  (V columns via odd-stride conflict-free scalar LDS) ----
#pragma unroll 8
        for (int k = 0; k < 64; k++) {
            float pp[4];
            *(float4*)pp = *(const float4*)&Ps[k * LQ + tq * 4];
            const float v0 = Vs[(tk +  0) * LV + k];
            const float v1 = Vs[(tk + 16) * LV + k];
            const float v2 = Vs[(tk + 32) * LV + k];
            const float v3 = Vs[(tk + 48) * LV + k];
#pragma unroll
            for (int j = 0; j < 4; j++) {
                o_r[0][j] += v0 * pp[j];
                o_r[1][j] += v1 * pp[j];
                o_r[2][j] += v2 * pp[j];
                o_r[3][j] += v3 * pp[j];
            }
        }
        __syncwarp();
    }

    // ---- epilogue: normalize and store ----
    float il[4];
#pragma unroll
    for (int j = 0; j < 4; j++) il[j] = 1.f / l_r[j];
#pragma unroll
    for (int i = 0; i < 4; i++) {
        float4 r;
        r.x = o_r[i][0] * il[0]; r.y = o_r[i][1] * il[1];
        r.z = o_r[i][2] * il[2]; r.w = o_r[i][3] * il[3];
        *(float4*)&Og[(size_t)(tk + 16 * i) * SEQ + tq * 4] = r;
    }
}

// ---------------------------------------------------------------------------
extern "C" void kernel_launch(void* const* d_in, const int* in_sizes, int n_in,
                              void* d_out, int out_size)
{
    const float* q   = (const float*)d_in[0];
    const float* k   = (const float*)d_in[1];
    const float* v   = (const float*)d_in[2];
    const float* msk = (const float*)d_in[3];
    const float* Wq  = (const float*)d_in[4];
    const float* bq  = (const float*)d_in[5];
    const float* Wk  = (const float*)d_in[6];
    const float* bk  = (const float*)d_in[7];
    const float* Wv  = (const float*)d_in[8];
    const float* bv  = (const float*)d_in[9];
    const float* Wo  = (const float*)d_in[10];
    const float* bo  = (const float*)d_in[11];
    float* out = (float*)d_out;

    void *pqp, *pkp, *pvp, *pat;
    cudaGetSymbolAddress(&pqp, g_qp);
    cudaGetSymbolAddress(&pkp, g_kp);
    cudaGetSymbolAddress(&pvp, g_vp);
    cudaGetSymbolAddress(&pat, g_at);

    cudaFuncSetAttribute(attn_kernel,
                         cudaFuncAttributeMaxDynamicSharedMemorySize,
                         ATTN_SMEM_BYTES);

    const float scale = 0.125f;  // dh^-0.5, dh = 64
    dim3 gp(SEQ / 128, EMB / 128, BATCH);
    proj_gemm<<<gp, 256>>>(Wq, q, bq, (float*)pqp, scale);
    proj_gemm<<<gp, 256>>>(Wk, k, bk, (float*)pkp, 1.f);
    proj_gemm<<<gp, 256>>>(Wv, v, bv, (float*)pvp, 1.f);

    dim3 ga(SEQ / 64, NH, BATCH);
    attn_kernel<<<ga, 256, ATTN_SMEM_BYTES>>>(
        (const float*)pqp, (const float*)pkp, (const float*)pvp, msk,
        (float*)pat);

    proj_gemm<<<gp, 256>>>(Wo, (const float*)pat, bo, out, 1.f);
}

// round 3
// speedup vs baseline: 1.3327x; 1.3327x over previous
#include <cuda_runtime.h>
#include <cstdint>

#define BATCH 2
#define EMB   1024
#define SEQ   2048
#define NH    16
#define DH    64
#define KDIM  1024

// ---------------- scratch (__device__ globals; no allocs allowed) -----------
__device__ float g_qp[(size_t)BATCH * EMB * SEQ];   // Q proj [E][S]
__device__ float g_kp[(size_t)BATCH * EMB * SEQ];   // K proj [E][S]
__device__ float g_vp[(size_t)BATCH * EMB * SEQ];   // V proj [E][S]
__device__ float g_at[(size_t)BATCH * EMB * SEQ];   // attn out [E][S]

// ---------------- mma.sync helpers ------------------------------------------
__device__ __forceinline__ uint32_t smem_u32(const void* p) {
    uint32_t a;
    asm("{ .reg .u64 t; cvta.to.shared.u64 t, %1; cvt.u32.u64 %0, t; }"
        : "=r"(a) : "l"(p));
    return a;
}

__device__ __forceinline__ void mma16816(float* c, const uint32_t* a, const uint32_t* b) {
    asm volatile(
        "mma.sync.aligned.m16n8k16.row.col.f32.bf16.bf16.f32 "
        "{%0,%1,%2,%3}, {%4,%5,%6,%7}, {%8,%9}, {%0,%1,%2,%3};"
        : "+f"(c[0]), "+f"(c[1]), "+f"(c[2]), "+f"(c[3])
        : "r"(a[0]), "r"(a[1]), "r"(a[2]), "r"(a[3]), "r"(b[0]), "r"(b[1]));
}

#define LDSM_X4(r0, r1, r2, r3, addr)                                          \
    asm volatile("ldmatrix.sync.aligned.m8n8.x4.shared.b16 {%0,%1,%2,%3}, [%4];" \
                 : "=r"(r0), "=r"(r1), "=r"(r2), "=r"(r3) : "r"(addr))

#define LDSM_X4T(r0, r1, r2, r3, addr)                                         \
    asm volatile("ldmatrix.sync.aligned.m8n8.x4.trans.shared.b16 {%0,%1,%2,%3}, [%4];" \
                 : "=r"(r0), "=r"(r1), "=r"(r2), "=r"(r3) : "r"(addr))

#define STS_V2(addr, a, b)                                                     \
    asm volatile("st.shared.v2.b32 [%0], {%1, %2};" :: "r"(addr), "r"(a), "r"(b) : "memory")

// pack: low half = a, high half = b (memory element order: a then b)
#define CVT_BF16X2(res, a, b)                                                  \
    asm("cvt.rn.bf16x2.f32 %0, %1, %2;" : "=r"(res) : "f"(b), "f"(a))

// split a float4 into bf16-hi pair regs and bf16-lo pair regs
__device__ __forceinline__ void split4(const float4 v, uint32_t& h0, uint32_t& h1,
                                       uint32_t& l0, uint32_t& l1) {
    CVT_BF16X2(h0, v.x, v.y);
    CVT_BF16X2(h1, v.z, v.w);
    const float r0 = v.x - __uint_as_float(h0 << 16);
    const float r1 = v.y - __uint_as_float(h0 & 0xffff0000u);
    const float r2 = v.z - __uint_as_float(h1 << 16);
    const float r3 = v.w - __uint_as_float(h1 & 0xffff0000u);
    CVT_BF16X2(l0, r0, r1);
    CVT_BF16X2(l1, r2, r3);
}

// ---------------- GEMM via mma.sync ------------------------------------------
// C[b][m][n] = alpha * (sum_k W[m][k] * X[b][k][n] + bias[m])
// A = W row-major (k contiguous)  -> plain ldmatrix
// B = X k-major tile [32k][128n]  -> ldmatrix.x4.trans
// CTA 128m x 128n, BK=32, 8 warps (wm 0..3 -> m 32-chunks, wn 0..1 -> n 64-chunks)
#define LA 40      // A smem pitch in bf16 elems
#define LB 136     // B smem pitch in bf16 elems
#define AH_OFF 0
#define AL_OFF 10240
#define BH_OFF 20480
#define BL_OFF 29184
#define BUF_BYTES 37888
#define BIAS_OFF  75776
#define GB_SMEM   76288

__global__ void __launch_bounds__(256) gemm_mma(
    const float* __restrict__ X, const float* __restrict__ W,
    const float* __restrict__ bias, float* __restrict__ C, float alpha)
{
    extern __shared__ char smg[];
    const uint32_t sb = smem_u32(smg);
    const int tid = threadIdx.x, wid = tid >> 5, lane = tid & 31;
    const int n0 = blockIdx.x * 128, m0 = blockIdx.y * 128;
    const float* Xb = X + (size_t)blockIdx.z * KDIM * SEQ;
    float*       Cb = C + (size_t)blockIdx.z * EMB * SEQ;
    float* bias_s = (float*)(smg + BIAS_OFF);
    if (tid < 128) bias_s[tid] = bias[m0 + tid];

    const int wm = wid & 3;     // m 32-chunk
    const int wn = wid >> 2;    // n 64-chunk

    float acc[2][8][4];
#pragma unroll
    for (int ms = 0; ms < 2; ms++)
#pragma unroll
        for (int nt = 0; nt < 8; nt++)
#pragma unroll
            for (int i = 0; i < 4; i++) acc[ms][nt][i] = 0.f;

    // ldmatrix per-lane address components
    const int arow = lane & 15, ak8 = (lane >> 4) * 8;          // A: rows, k-half
    const int bj = lane >> 3, br = lane & 7;                    // B matrices
    const int bk = (bj & 1) * 8 + br, bn8 = (bj >> 1) * 8;      // B: k row, n-half

    float4 ra[4], rb[4];

    // ---- global tile load into regs ----
#define LOADG(kt) do {                                                         \
    _Pragma("unroll")                                                          \
    for (int i = 0; i < 4; i++) {                                              \
        const int e = i * 256 + tid;                                           \
        const int r = e >> 3, c = e & 7;                                       \
        ra[i] = *(const float4*)&W[(size_t)(m0 + r) * KDIM + (kt) * 32 + c * 4]; \
    }                                                                          \
    _Pragma("unroll")                                                          \
    for (int i = 0; i < 4; i++) {                                              \
        const int e = i * 256 + tid;                                           \
        const int r = e >> 5, c = e & 31;                                      \
        rb[i] = *(const float4*)&Xb[(size_t)((kt) * 32 + r) * SEQ + n0 + c * 4]; \
    }                                                                          \
} while (0)

    // ---- regs -> smem (convert to bf16 hi/lo) ----
#define STORES(buf) do {                                                       \
    const uint32_t base = sb + (buf) * BUF_BYTES;                              \
    _Pragma("unroll")                                                          \
    for (int i = 0; i < 4; i++) {                                              \
        const int e = i * 256 + tid;                                           \
        const int r = e >> 3, c = e & 7;                                       \
        uint32_t h0, h1, l0, l1;                                               \
        split4(ra[i], h0, h1, l0, l1);                                         \
        const uint32_t off = (uint32_t)(r * LA + c * 4) * 2;                   \
        STS_V2(base + AH_OFF + off, h0, h1);                                   \
        STS_V2(base + AL_OFF + off, l0, l1);                                   \
    }                                                                          \
    _Pragma("unroll")                                                          \
    for (int i = 0; i < 4; i++) {                                              \
        const int e = i * 256 + tid;                                           \
        const int r = e >> 5, c = e & 31;                                      \
        uint32_t h0, h1, l0, l1;                                               \
        split4(rb[i], h0, h1, l0, l1);                                         \
        const uint32_t off = (uint32_t)(r * LB + c * 4) * 2;                   \
        STS_V2(base + BH_OFF + off, h0, h1);                                   \
        STS_V2(base + BL_OFF + off, l0, l1);                                   \
    }                                                                          \
} while (0)

    LOADG(0);
    STORES(0);
    __syncthreads();

    const int NKT = KDIM / 32;
    for (int kt = 0; kt < NKT; kt++) {
        if (kt + 1 < NKT) LOADG(kt + 1);

        const uint32_t base = sb + (kt & 1) * BUF_BYTES;
#pragma unroll
        for (int ks = 0; ks < 2; ks++) {
            // A fragments (hi and lo) for the two 16-row subtiles
            uint32_t aF[2][4], aL[2][4];
#pragma unroll
            for (int ms = 0; ms < 2; ms++) {
                const uint32_t ao = (uint32_t)((wm * 32 + ms * 16 + arow) * LA
                                               + ks * 16 + ak8) * 2;
                LDSM_X4(aF[ms][0], aF[ms][1], aF[ms][2], aF[ms][3], base + AH_OFF + ao);
                LDSM_X4(aL[ms][0], aL[ms][1], aL[ms][2], aL[ms][3], base + AL_OFF + ao);
            }
#pragma unroll
            for (int nt16 = 0; nt16 < 4; nt16++) {
                uint32_t bH[4], bL[4];
                const uint32_t bo = (uint32_t)((ks * 16 + bk) * LB
                                               + wn * 64 + nt16 * 16 + bn8) * 2;
                LDSM_X4T(bH[0], bH[1], bH[2], bH[3], base + BH_OFF + bo);
                LDSM_X4T(bL[0], bL[1], bL[2], bL[3], base + BL_OFF + bo);
#pragma unroll
                for (int ms = 0; ms < 2; ms++) {
#pragma unroll
                    for (int s = 0; s < 2; s++) {
                        float* a4 = acc[ms][nt16 * 2 + s];
                        mma16816(a4, aF[ms], &bH[s * 2]);   // hi*hi
                        mma16816(a4, aF[ms], &bL[s * 2]);   // hi*lo
                        mma16816(a4, aL[ms], &bH[s * 2]);   // lo*hi
                    }
                }
            }
        }
        __syncthreads();
        if (kt + 1 < NKT) {
            STORES((kt + 1) & 1);
            __syncthreads();
        }
    }

    // ---- epilogue: accs -> smem [128m][128n] -> coalesced global ----
    __syncthreads();
    float* Cs = (float*)smg;                 // 128 x 132 floats
    {
        const int rr = lane >> 2, cc = (lane & 3) * 2;
#pragma unroll
        for (int ms = 0; ms < 2; ms++)
#pragma unroll
            for (int nt = 0; nt < 8; nt++) {
                const int r = wm * 32 + ms * 16 + rr;
                const int c = wn * 64 + nt * 8 + cc;
                Cs[r * 132 + c]           = acc[ms][nt][0];
                Cs[r * 132 + c + 1]       = acc[ms][nt][1];
                Cs[(r + 8) * 132 + c]     = acc[ms][nt][2];
                Cs[(r + 8) * 132 + c + 1] = acc[ms][nt][3];
            }
    }
    __syncthreads();
#pragma unroll
    for (int i = 0; i < 16; i++) {
        const int e = i * 256 + tid;
        const int r = e >> 5, c = e & 31;
        float4 v = *(const float4*)&Cs[r * 132 + c * 4];
        const float bi = bias_s[r];
        v.x = alpha * (v.x + bi); v.y = alpha * (v.y + bi);
        v.z = alpha * (v.z + bi); v.w = alpha * (v.w + bi);
        *(float4*)&Cb[(size_t)(m0 + r) * SEQ + n0 + c * 4] = v;
    }
}

// ---------------- fused SIMT attention (validated in R1) ---------------------
#define LQ 68
#define LV 65
static const int ATTN_SMEM_BYTES = (3 * 64 * LQ + 64 * LV) * (int)sizeof(float);

__global__ void __launch_bounds__(256) attn_kernel(
    const float* __restrict__ QP, const float* __restrict__ KP,
    const float* __restrict__ VP, const float* __restrict__ MASK,
    float* __restrict__ OUTP)
{
    extern __shared__ float sma[];
    float* Qs = sma;
    float* Ks = Qs + 64 * LQ;
    float* Ps = Ks + 64 * LQ;
    float* Vs = Ps + 64 * LQ;

    const int tid = threadIdx.x;
    const int b = blockIdx.z, h = blockIdx.y;
    const int q0 = blockIdx.x * 64;

    const float* Qg = QP + ((size_t)b * EMB + h * DH) * SEQ + q0;
    const float* Kg = KP + ((size_t)b * EMB + h * DH) * SEQ;
    const float* Vg = VP + ((size_t)b * EMB + h * DH) * SEQ;
    const float* Mg = MASK + (size_t)b * SEQ * SEQ + q0;
    float*       Og = OUTP + ((size_t)b * EMB + h * DH) * SEQ + q0;

    const int tk = tid & 15;
    const int tq = tid >> 4;

#pragma unroll
    for (int it = 0; it < 4; it++) {
        const int e = tid + it * 256;
        const int c = e >> 4, x4 = (e & 15) * 4;
        *(float4*)&Qs[c * LQ + x4] = *(const float4*)&Qg[(size_t)c * SEQ + x4];
    }

    float m_r[4], l_r[4], o_r[4][4];
#pragma unroll
    for (int j = 0; j < 4; j++) { m_r[j] = -1e30f; l_r[j] = 0.f; }
#pragma unroll
    for (int i = 0; i < 4; i++)
#pragma unroll
        for (int j = 0; j < 4; j++) o_r[i][j] = 0.f;

    for (int kt = 0; kt < SEQ / 64; kt++) {
        const int k0 = kt * 64;
        __syncthreads();
#pragma unroll
        for (int it = 0; it < 4; it++) {
            const int e = tid + it * 256;
            const int c = e >> 4, x4 = (e & 15) * 4;
            *(float4*)&Ks[c * LQ + x4] =
                *(const float4*)&Kg[(size_t)c * SEQ + k0 + x4];
            float4 vv = *(const float4*)&Vg[(size_t)c * SEQ + k0 + x4];
            Vs[c * LV + x4 + 0] = vv.x; Vs[c * LV + x4 + 1] = vv.y;
            Vs[c * LV + x4 + 2] = vv.z; Vs[c * LV + x4 + 3] = vv.w;
        }
        __syncthreads();

        float acc[4][4];
#pragma unroll
        for (int i = 0; i < 4; i++) {
            float4 mr = *(const float4*)&Mg[(size_t)(k0 + tk * 4 + i) * SEQ + tq * 4];
            acc[i][0] = mr.x; acc[i][1] = mr.y; acc[i][2] = mr.z; acc[i][3] = mr.w;
        }
#pragma unroll 8
        for (int c = 0; c < 64; c++) {
            float kk[4], qq[4];
            *(float4*)kk = *(const float4*)&Ks[c * LQ + tk * 4];
            *(float4*)qq = *(const float4*)&Qs[c * LQ + tq * 4];
#pragma unroll
            for (int i = 0; i < 4; i++)
#pragma unroll
                for (int j = 0; j < 4; j++)
                    acc[i][j] += kk[i] * qq[j];
        }

        float p[4][4], fs[4];
#pragma unroll
        for (int j = 0; j < 4; j++) {
            float mx = fmaxf(fmaxf(acc[0][j], acc[1][j]), fmaxf(acc[2][j], acc[3][j]));
#pragma unroll
            for (int off = 1; off < 16; off <<= 1)
                mx = fmaxf(mx, __shfl_xor_sync(0xffffffffu, mx, off));
            const float mnew = fmaxf(m_r[j], mx);
            fs[j] = __expf(m_r[j] - mnew);
            float ts = 0.f;
#pragma unroll
            for (int i = 0; i < 4; i++) {
                p[i][j] = __expf(acc[i][j] - mnew);
                ts += p[i][j];
            }
#pragma unroll
            for (int off = 1; off < 16; off <<= 1)
                ts += __shfl_xor_sync(0xffffffffu, ts, off);
            l_r[j] = l_r[j] * fs[j] + ts;
            m_r[j] = mnew;
        }

#pragma unroll
        for (int i = 0; i < 4; i++)
            *(float4*)&Ps[(tk * 4 + i) * LQ + tq * 4] =
                make_float4(p[i][0], p[i][1], p[i][2], p[i][3]);

#pragma unroll
        for (int i = 0; i < 4; i++)
#pragma unroll
            for (int j = 0; j < 4; j++) o_r[i][j] *= fs[j];
        __syncwarp();

#pragma unroll 8
        for (int k = 0; k < 64; k++) {
            float pp[4];
            *(float4*)pp = *(const float4*)&Ps[k * LQ + tq * 4];
            const float v0 = Vs[(tk +  0) * LV + k];
            const float v1 = Vs[(tk + 16) * LV + k];
            const float v2 = Vs[(tk + 32) * LV + k];
            const float v3 = Vs[(tk + 48) * LV + k];
#pragma unroll
            for (int j = 0; j < 4; j++) {
                o_r[0][j] += v0 * pp[j];
                o_r[1][j] += v1 * pp[j];
                o_r[2][j] += v2 * pp[j];
                o_r[3][j] += v3 * pp[j];
            }
        }
        __syncwarp();
    }

    float il[4];
#pragma unroll
    for (int j = 0; j < 4; j++) il[j] = 1.f / l_r[j];
#pragma unroll
    for (int i = 0; i < 4; i++) {
        float4 r;
        r.x = o_r[i][0] * il[0]; r.y = o_r[i][1] * il[1];
        r.z = o_r[i][2] * il[2]; r.w = o_r[i][3] * il[3];
        *(float4*)&Og[(size_t)(tk + 16 * i) * SEQ + tq * 4] = r;
    }
}

// ---------------------------------------------------------------------------
extern "C" void kernel_launch(void* const* d_in, const int* in_sizes, int n_in,
                              void* d_out, int out_size)
{
    const float* q   = (const float*)d_in[0];
    const float* k   = (const float*)d_in[1];
    const float* v   = (const float*)d_in[2];
    const float* msk = (const float*)d_in[3];
    const float* Wq  = (const float*)d_in[4];
    const float* bq  = (const float*)d_in[5];
    const float* Wk  = (const float*)d_in[6];
    const float* bk  = (const float*)d_in[7];
    const float* Wv  = (const float*)d_in[8];
    const float* bv  = (const float*)d_in[9];
    const float* Wo  = (const float*)d_in[10];
    const float* bo  = (const float*)d_in[11];
    float* out = (float*)d_out;

    void *pqp, *pkp, *pvp, *pat;
    cudaGetSymbolAddress(&pqp, g_qp);
    cudaGetSymbolAddress(&pkp, g_kp);
    cudaGetSymbolAddress(&pvp, g_vp);
    cudaGetSymbolAddress(&pat, g_at);

    cudaFuncSetAttribute(gemm_mma, cudaFuncAttributeMaxDynamicSharedMemorySize, GB_SMEM);
    cudaFuncSetAttribute(attn_kernel, cudaFuncAttributeMaxDynamicSharedMemorySize,
                         ATTN_SMEM_BYTES);

    dim3 gg(SEQ / 128, EMB / 128, BATCH);
    gemm_mma<<<gg, 256, GB_SMEM>>>(q, Wq, bq, (float*)pqp, 0.125f);
    gemm_mma<<<gg, 256, GB_SMEM>>>(k, Wk, bk, (float*)pkp, 1.0f);
    gemm_mma<<<gg, 256, GB_SMEM>>>(v, Wv, bv, (float*)pvp, 1.0f);

    dim3 ga(SEQ / 64, NH, BATCH);
    attn_kernel<<<ga, 256, ATTN_SMEM_BYTES>>>(
        (const float*)pqp, (const float*)pkp, (const float*)pvp, msk, (float*)pat);

    gemm_mma<<<gg, 256, GB_SMEM>>>((const float*)pat, Wo, bo, out, 1.0f);
}